// round 1
// baseline (speedup 1.0000x reference)
#include <cuda_runtime.h>
#include <math.h>

#define Bc 2
#define Sc 4096
#define DMc 768
#define Hc 12
#define HDc 64
#define BHc (Bc*Hc)

// Scratch (allocation-free rule: __device__ globals)
__device__ float g_q[(size_t)BHc*Sc*HDc];
__device__ float g_k[(size_t)BHc*Sc*HDc];
__device__ float g_v[(size_t)BHc*Sc*HDc];
__device__ float g_attn[(size_t)Bc*Sc*DMc];
__device__ float g_y[(size_t)Bc*Sc*DMc];

// ---------------------------------------------------------------------------
// GEMM:  C[M,N] = X[M,K] @ W[N,K]^T (+bias)  ; M=8192, N=K=768
// MODE 0: write q/k/v scratch in [b,h,s,d] layout (sel picks target), +bias
// MODE 1: write g_y[row,col] = acc + resid[row,col]   (X is g_attn)
// ---------------------------------------------------------------------------
template <int MODE>
__global__ __launch_bounds__(256) void gemm_nt(const float* __restrict__ Xin,
                                               const float* __restrict__ W,
                                               const float* __restrict__ bias,
                                               const float* __restrict__ resid,
                                               int sel) {
    __shared__ __align__(16) float Xs[16][68];
    __shared__ __align__(16) float Ws[16][68];

    const float* X = (MODE == 1) ? g_attn : Xin;
    float* dst;
    if (MODE == 0) dst = (sel == 0) ? g_q : (sel == 1) ? g_k : g_v;
    else           dst = g_y;

    int tid = threadIdx.x;
    int tx = tid & 15, ty = tid >> 4;
    int rowBase = blockIdx.y * 64;
    int colBase = blockIdx.x * 64;

    int loadRow = tid >> 2;          // 0..63
    int loadK   = (tid & 3) * 4;     // 0,4,8,12

    const float* xp = X + (size_t)(rowBase + loadRow) * DMc + loadK;
    const float* wp = W + (size_t)(colBase + loadRow) * DMc + loadK;

    float acc[4][4];
#pragma unroll
    for (int i = 0; i < 4; i++)
#pragma unroll
        for (int j = 0; j < 4; j++) acc[i][j] = 0.f;

    for (int kb = 0; kb < DMc; kb += 16) {
        float4 xv = *(const float4*)(xp + kb);
        float4 wv = *(const float4*)(wp + kb);
        __syncthreads();
        Xs[loadK + 0][loadRow] = xv.x;
        Xs[loadK + 1][loadRow] = xv.y;
        Xs[loadK + 2][loadRow] = xv.z;
        Xs[loadK + 3][loadRow] = xv.w;
        Ws[loadK + 0][loadRow] = wv.x;
        Ws[loadK + 1][loadRow] = wv.y;
        Ws[loadK + 2][loadRow] = wv.z;
        Ws[loadK + 3][loadRow] = wv.w;
        __syncthreads();
#pragma unroll
        for (int kk = 0; kk < 16; kk++) {
            float4 a = *(const float4*)&Xs[kk][ty * 4];
            float4 b = *(const float4*)&Ws[kk][tx * 4];
            float av[4] = {a.x, a.y, a.z, a.w};
            float bv[4] = {b.x, b.y, b.z, b.w};
#pragma unroll
            for (int i = 0; i < 4; i++)
#pragma unroll
                for (int j = 0; j < 4; j++)
                    acc[i][j] = fmaf(av[i], bv[j], acc[i][j]);
        }
    }

#pragma unroll
    for (int i = 0; i < 4; i++) {
        int row = rowBase + ty * 4 + i;
#pragma unroll
        for (int j = 0; j < 4; j++) {
            int col = colBase + tx * 4 + j;
            float c = acc[i][j];
            if (MODE == 0) {
                c += bias[col];
                int b_ = row >> 12;       // /S
                int s_ = row & (Sc - 1);
                int h_ = col >> 6;        // /HD
                int d_ = col & (HDc - 1);
                dst[(((size_t)(b_ * Hc + h_)) * Sc + s_) * HDc + d_] = c;
            } else {
                size_t o = (size_t)row * DMc + col;
                dst[o] = c + resid[o];
            }
        }
    }
}

// ---------------------------------------------------------------------------
// RoPE: in-place on g_q (with 1/HD scaling folded in) and g_k.
// grid.y = 0 -> q, 1 -> k.  One thread per (b,h,s) row of 64 dims.
// ---------------------------------------------------------------------------
__global__ __launch_bounds__(256) void rope_kernel(const float* __restrict__ cosp,
                                                   const float* __restrict__ sinp) {
    int idx = blockIdx.x * blockDim.x + threadIdx.x;   // 0 .. B*H*S-1
    if (idx >= BHc * Sc) return;
    float* arr  = (blockIdx.y == 0) ? g_q : g_k;
    float scale = (blockIdx.y == 0) ? (1.0f / (float)HDc) : 1.0f;
    int s = idx & (Sc - 1);
    float* p = arr + (size_t)idx * HDc;
    const float4* cp = (const float4*)(cosp + (size_t)s * HDc);
    const float4* sp = (const float4*)(sinp + (size_t)s * HDc);
#pragma unroll
    for (int d4 = 0; d4 < 8; d4++) {
        float4 x1 = *(float4*)(p + d4 * 4);
        float4 x2 = *(float4*)(p + 32 + d4 * 4);
        float4 c  = cp[d4];          // cos[d] == cos[d+32] by construction
        float4 sn = sp[d4];
        float4 o1, o2;
        o1.x = (x1.x * c.x - x2.x * sn.x) * scale;
        o1.y = (x1.y * c.y - x2.y * sn.y) * scale;
        o1.z = (x1.z * c.z - x2.z * sn.z) * scale;
        o1.w = (x1.w * c.w - x2.w * sn.w) * scale;
        o2.x = (x2.x * c.x + x1.x * sn.x) * scale;
        o2.y = (x2.y * c.y + x1.y * sn.y) * scale;
        o2.z = (x2.z * c.z + x1.z * sn.z) * scale;
        o2.w = (x2.w * c.w + x1.w * sn.w) * scale;
        *(float4*)(p + d4 * 4)      = o1;
        *(float4*)(p + 32 + d4 * 4) = o2;
    }
}

// ---------------------------------------------------------------------------
// Flash attention (fp32, streaming softmax).
// grid = (S/128, B*H); 128 threads; 1 thread = 1 query row.
// K/V tiles of 32 rows in smem, broadcast LDS.128 reads -> FFMA-bound.
// Writes g_attn in [b, s, h*64+d] layout.
// ---------------------------------------------------------------------------
#define FBN 32
__global__ __launch_bounds__(128) void flash_attn_kernel() {
    __shared__ __align__(16) float4 ks[FBN][16];
    __shared__ __align__(16) float4 vs[FBN][16];

    int bh = blockIdx.y;
    int qrow = blockIdx.x * 128 + threadIdx.x;
    const float4* qp = (const float4*)(g_q + ((size_t)bh * Sc + qrow) * HDc);
    const float4* kb = (const float4*)(g_k + (size_t)bh * Sc * HDc);
    const float4* vb = (const float4*)(g_v + (size_t)bh * Sc * HDc);

    float qr[64], o[64];
#pragma unroll
    for (int d4 = 0; d4 < 16; d4++) {
        float4 t = qp[d4];
        qr[4 * d4 + 0] = t.x; qr[4 * d4 + 1] = t.y;
        qr[4 * d4 + 2] = t.z; qr[4 * d4 + 3] = t.w;
    }
#pragma unroll
    for (int d = 0; d < 64; d++) o[d] = 0.f;

    float m = -INFINITY, l = 0.f;
    int t = threadIdx.x;

    for (int j0 = 0; j0 < Sc; j0 += FBN) {
        __syncthreads();
#pragma unroll
        for (int u = 0; u < 4; u++) {
            int idx = u * 128 + t;           // 0..511
            int j = idx >> 4, d4 = idx & 15;
            ks[j][d4] = kb[(size_t)(j0 + j) * 16 + d4];
            vs[j][d4] = vb[(size_t)(j0 + j) * 16 + d4];
        }
        __syncthreads();

        float p[FBN];
        float mt = -INFINITY;
#pragma unroll
        for (int j = 0; j < FBN; j++) {
            float s = 0.f;
#pragma unroll
            for (int d4 = 0; d4 < 16; d4++) {
                float4 kk = ks[j][d4];
                s = fmaf(qr[4 * d4 + 0], kk.x, s);
                s = fmaf(qr[4 * d4 + 1], kk.y, s);
                s = fmaf(qr[4 * d4 + 2], kk.z, s);
                s = fmaf(qr[4 * d4 + 3], kk.w, s);
            }
            p[j] = s;
            mt = fmaxf(mt, s);
        }
        float newm = fmaxf(m, mt);
        float corr = __expf(m - newm);       // 0 on first tile (m = -inf)
        float ps = 0.f;
#pragma unroll
        for (int j = 0; j < FBN; j++) {
            p[j] = __expf(p[j] - newm);
            ps += p[j];
        }
        l = l * corr + ps;
#pragma unroll
        for (int d = 0; d < 64; d++) o[d] *= corr;
#pragma unroll
        for (int j = 0; j < FBN; j++) {
            float pj = p[j];
#pragma unroll
            for (int d4 = 0; d4 < 16; d4++) {
                float4 vv = vs[j][d4];
                o[4 * d4 + 0] = fmaf(pj, vv.x, o[4 * d4 + 0]);
                o[4 * d4 + 1] = fmaf(pj, vv.y, o[4 * d4 + 1]);
                o[4 * d4 + 2] = fmaf(pj, vv.z, o[4 * d4 + 2]);
                o[4 * d4 + 3] = fmaf(pj, vv.w, o[4 * d4 + 3]);
            }
        }
        m = newm;
    }

    float inv = 1.f / l;
    int b_ = bh / Hc, h_ = bh % Hc;
    float4* op = (float4*)(g_attn + ((size_t)(b_ * Sc + qrow)) * DMc + h_ * HDc);
#pragma unroll
    for (int d4 = 0; d4 < 16; d4++) {
        float4 r;
        r.x = o[4 * d4 + 0] * inv;
        r.y = o[4 * d4 + 1] * inv;
        r.z = o[4 * d4 + 2] * inv;
        r.w = o[4 * d4 + 3] * inv;
        op[d4] = r;
    }
}

// ---------------------------------------------------------------------------
// LayerNorm over last dim (768), one block per row.
// ---------------------------------------------------------------------------
__global__ __launch_bounds__(256) void ln_kernel(const float* __restrict__ g,
                                                 const float* __restrict__ bb,
                                                 float* __restrict__ out) {
    int row = blockIdx.x;
    const float* yp = g_y + (size_t)row * DMc;
    int tid = threadIdx.x;
    float v0 = yp[tid], v1 = yp[tid + 256], v2 = yp[tid + 512];
    float s = v0 + v1 + v2;

    __shared__ float red[8];
    __shared__ float bc;
#pragma unroll
    for (int o_ = 16; o_ > 0; o_ >>= 1) s += __shfl_xor_sync(0xffffffffu, s, o_);
    if ((tid & 31) == 0) red[tid >> 5] = s;
    __syncthreads();
    if (tid == 0) {
        float tsum = 0.f;
#pragma unroll
        for (int i = 0; i < 8; i++) tsum += red[i];
        bc = tsum;
    }
    __syncthreads();
    float mu = bc * (1.0f / (float)DMc);
    float d0 = v0 - mu, d1 = v1 - mu, d2 = v2 - mu;
    float sq = d0 * d0 + d1 * d1 + d2 * d2;
    __syncthreads();
#pragma unroll
    for (int o_ = 16; o_ > 0; o_ >>= 1) sq += __shfl_xor_sync(0xffffffffu, sq, o_);
    if ((tid & 31) == 0) red[tid >> 5] = sq;
    __syncthreads();
    if (tid == 0) {
        float tsum = 0.f;
#pragma unroll
        for (int i = 0; i < 8; i++) tsum += red[i];
        bc = tsum;
    }
    __syncthreads();
    float var = bc * (1.0f / (float)DMc);
    float inv = rsqrtf(var + 1e-12f);
    size_t base = (size_t)row * DMc;
    out[base + tid]       = d0 * inv * g[tid]       + bb[tid];
    out[base + tid + 256] = d1 * inv * g[tid + 256] + bb[tid + 256];
    out[base + tid + 512] = d2 * inv * g[tid + 512] + bb[tid + 512];
}

// ---------------------------------------------------------------------------
extern "C" void kernel_launch(void* const* d_in, const int* in_sizes, int n_in,
                              void* d_out, int out_size) {
    const float* hidden = (const float*)d_in[0];
    const float* cosp   = (const float*)d_in[1];
    const float* sinp   = (const float*)d_in[2];
    const float* Wq     = (const float*)d_in[3];
    const float* bq     = (const float*)d_in[4];
    const float* Wk     = (const float*)d_in[5];
    const float* bk     = (const float*)d_in[6];
    const float* Wv     = (const float*)d_in[7];
    const float* bv     = (const float*)d_in[8];
    const float* Wo     = (const float*)d_in[9];
    const float* ln_g   = (const float*)d_in[10];
    const float* ln_b   = (const float*)d_in[11];
    float* out = (float*)d_out;

    dim3 ggrid(DMc / 64, (Bc * Sc) / 64);   // (12, 128)
    gemm_nt<0><<<ggrid, 256>>>(hidden, Wq, bq, nullptr, 0);
    gemm_nt<0><<<ggrid, 256>>>(hidden, Wk, bk, nullptr, 1);
    gemm_nt<0><<<ggrid, 256>>>(hidden, Wv, bv, nullptr, 2);

    dim3 rgrid((BHc * Sc + 255) / 256, 2);
    rope_kernel<<<rgrid, 256>>>(cosp, sinp);

    dim3 agrid(Sc / 128, BHc);              // (32, 24)
    flash_attn_kernel<<<agrid, 128>>>();

    gemm_nt<1><<<ggrid, 256>>>(nullptr, Wo, nullptr, hidden, 0);

    ln_kernel<<<Bc * Sc, 256>>>(ln_g, ln_b, out);
}

// round 2
// speedup vs baseline: 3.0659x; 3.0659x over previous
#include <cuda_runtime.h>
#include <cuda_bf16.h>
#include <math.h>
#include <stdint.h>

#define Bc 2
#define Sc 4096
#define DMc 768
#define Hc 12
#define HDc 64
#define BHc (Bc*Hc)

// Scratch (allocation-free rule: __device__ globals)
__device__ float g_q[(size_t)BHc*Sc*HDc];            // fp32 q (pre-RoPE)
__device__ float g_k[(size_t)BHc*Sc*HDc];            // fp32 k (pre-RoPE)
__device__ __nv_bfloat16 g_qh[(size_t)BHc*Sc*HDc];   // bf16 q (RoPE'd, * 1/64)
__device__ __nv_bfloat16 g_kh[(size_t)BHc*Sc*HDc];   // bf16 k (RoPE'd)
__device__ __nv_bfloat16 g_vh[(size_t)BHc*Sc*HDc];   // bf16 v
__device__ float g_attn[(size_t)Bc*Sc*DMc];
__device__ float g_y[(size_t)Bc*Sc*DMc];

// ---------------------------------------------------------------------------
// GEMM:  C[M,N] = X[M,K] @ W[N,K]^T (+bias)  ; M=8192, N=K=768
// MODE 0: sel 0/1 -> fp32 g_q/g_k in [b,h,s,d]; sel 2 -> bf16 g_vh
// MODE 1: g_y[row,col] = acc + resid[row,col]   (X is g_attn)
// ---------------------------------------------------------------------------
template <int MODE>
__global__ __launch_bounds__(256) void gemm_nt(const float* __restrict__ Xin,
                                               const float* __restrict__ W,
                                               const float* __restrict__ bias,
                                               const float* __restrict__ resid,
                                               int sel) {
    __shared__ __align__(16) float Xs[16][68];
    __shared__ __align__(16) float Ws[16][68];

    const float* X = (MODE == 1) ? g_attn : Xin;
    float* dst = nullptr;
    if (MODE == 0) dst = (sel == 0) ? g_q : g_k;
    else           dst = g_y;

    int tid = threadIdx.x;
    int tx = tid & 15, ty = tid >> 4;
    int rowBase = blockIdx.y * 64;
    int colBase = blockIdx.x * 64;

    int loadRow = tid >> 2;          // 0..63
    int loadK   = (tid & 3) * 4;     // 0,4,8,12

    const float* xp = X + (size_t)(rowBase + loadRow) * DMc + loadK;
    const float* wp = W + (size_t)(colBase + loadRow) * DMc + loadK;

    float acc[4][4];
#pragma unroll
    for (int i = 0; i < 4; i++)
#pragma unroll
        for (int j = 0; j < 4; j++) acc[i][j] = 0.f;

    for (int kb = 0; kb < DMc; kb += 16) {
        float4 xv = *(const float4*)(xp + kb);
        float4 wv = *(const float4*)(wp + kb);
        __syncthreads();
        Xs[loadK + 0][loadRow] = xv.x;
        Xs[loadK + 1][loadRow] = xv.y;
        Xs[loadK + 2][loadRow] = xv.z;
        Xs[loadK + 3][loadRow] = xv.w;
        Ws[loadK + 0][loadRow] = wv.x;
        Ws[loadK + 1][loadRow] = wv.y;
        Ws[loadK + 2][loadRow] = wv.z;
        Ws[loadK + 3][loadRow] = wv.w;
        __syncthreads();
#pragma unroll
        for (int kk = 0; kk < 16; kk++) {
            float4 a = *(const float4*)&Xs[kk][ty * 4];
            float4 b = *(const float4*)&Ws[kk][tx * 4];
            float av[4] = {a.x, a.y, a.z, a.w};
            float bv[4] = {b.x, b.y, b.z, b.w};
#pragma unroll
            for (int i = 0; i < 4; i++)
#pragma unroll
                for (int j = 0; j < 4; j++)
                    acc[i][j] = fmaf(av[i], bv[j], acc[i][j]);
        }
    }

#pragma unroll
    for (int i = 0; i < 4; i++) {
        int row = rowBase + ty * 4 + i;
#pragma unroll
        for (int j = 0; j < 4; j++) {
            int col = colBase + tx * 4 + j;
            float c = acc[i][j];
            if (MODE == 0) {
                c += bias[col];
                int b_ = row >> 12;       // /S
                int s_ = row & (Sc - 1);
                int h_ = col >> 6;        // /HD
                int d_ = col & (HDc - 1);
                size_t o = (((size_t)(b_ * Hc + h_)) * Sc + s_) * HDc + d_;
                if (sel == 2) g_vh[o] = __float2bfloat16(c);
                else          dst[o]  = c;
            } else {
                size_t o = (size_t)row * DMc + col;
                dst[o] = c + resid[o];
            }
        }
    }
}

// ---------------------------------------------------------------------------
// RoPE (fp32 in -> bf16 out). grid.y 0 -> q (scaled by 1/64), 1 -> k.
// ---------------------------------------------------------------------------
__global__ __launch_bounds__(256) void rope_kernel(const float* __restrict__ cosp,
                                                   const float* __restrict__ sinp) {
    int idx = blockIdx.x * blockDim.x + threadIdx.x;   // 0 .. B*H*S-1
    if (idx >= BHc * Sc) return;
    const float* arr = (blockIdx.y == 0) ? g_q : g_k;
    __nv_bfloat16* oarr = (blockIdx.y == 0) ? g_qh : g_kh;
    float scale = (blockIdx.y == 0) ? (1.0f / (float)HDc) : 1.0f;
    int s = idx & (Sc - 1);
    const float* p = arr + (size_t)idx * HDc;
    __nv_bfloat16* po = oarr + (size_t)idx * HDc;
    const float4* cp = (const float4*)(cosp + (size_t)s * HDc);
    const float4* sp = (const float4*)(sinp + (size_t)s * HDc);
#pragma unroll
    for (int d4 = 0; d4 < 8; d4++) {
        float4 x1 = *(const float4*)(p + d4 * 4);
        float4 x2 = *(const float4*)(p + 32 + d4 * 4);
        float4 c  = cp[d4];
        float4 sn = sp[d4];
        float4 o1, o2;
        o1.x = (x1.x * c.x - x2.x * sn.x) * scale;
        o1.y = (x1.y * c.y - x2.y * sn.y) * scale;
        o1.z = (x1.z * c.z - x2.z * sn.z) * scale;
        o1.w = (x1.w * c.w - x2.w * sn.w) * scale;
        o2.x = (x2.x * c.x + x1.x * sn.x) * scale;
        o2.y = (x2.y * c.y + x1.y * sn.y) * scale;
        o2.z = (x2.z * c.z + x1.z * sn.z) * scale;
        o2.w = (x2.w * c.w + x1.w * sn.w) * scale;
        __nv_bfloat162 a0 = __floats2bfloat162_rn(o1.x, o1.y);
        __nv_bfloat162 a1 = __floats2bfloat162_rn(o1.z, o1.w);
        __nv_bfloat162 b0 = __floats2bfloat162_rn(o2.x, o2.y);
        __nv_bfloat162 b1 = __floats2bfloat162_rn(o2.z, o2.w);
        *(__nv_bfloat162*)(po + d4 * 4 + 0)      = a0;
        *(__nv_bfloat162*)(po + d4 * 4 + 2)      = a1;
        *(__nv_bfloat162*)(po + 32 + d4 * 4 + 0) = b0;
        *(__nv_bfloat162*)(po + 32 + d4 * 4 + 2) = b1;
    }
}

// ---------------------------------------------------------------------------
// Flash attention with bf16 mma.sync (m16n8k16), fp32 accum + fp32 softmax.
// CTA: 128 threads (4 warps), 64 query rows (16/warp). Key tile = 64.
// ---------------------------------------------------------------------------
#define SSTR 72   // smem row stride in halves (64 + 8 pad -> conflict-free ldmatrix)

__device__ __forceinline__ uint32_t pack_bf16(float lo, float hi) {
    __nv_bfloat162 h = __floats2bfloat162_rn(lo, hi);
    return *reinterpret_cast<uint32_t*>(&h);
}

#define LDSM4(r0,r1,r2,r3,addr) \
    asm volatile("ldmatrix.sync.aligned.m8n8.x4.shared.b16 {%0,%1,%2,%3},[%4];" \
                 : "=r"(r0),"=r"(r1),"=r"(r2),"=r"(r3) : "r"(addr))
#define LDSM4T(r0,r1,r2,r3,addr) \
    asm volatile("ldmatrix.sync.aligned.m8n8.x4.trans.shared.b16 {%0,%1,%2,%3},[%4];" \
                 : "=r"(r0),"=r"(r1),"=r"(r2),"=r"(r3) : "r"(addr))
#define MMA16816(c, a, b0, b1) \
    asm volatile("mma.sync.aligned.m16n8k16.row.col.f32.bf16.bf16.f32 " \
                 "{%0,%1,%2,%3},{%4,%5,%6,%7},{%8,%9},{%0,%1,%2,%3};" \
                 : "+f"((c)[0]),"+f"((c)[1]),"+f"((c)[2]),"+f"((c)[3]) \
                 : "r"((a)[0]),"r"((a)[1]),"r"((a)[2]),"r"((a)[3]),"r"(b0),"r"(b1))

__global__ __launch_bounds__(128) void flash_mma_kernel() {
    __shared__ __align__(16) __nv_bfloat16 Qs[64 * SSTR];
    __shared__ __align__(16) __nv_bfloat16 Ks[64 * SSTR];
    __shared__ __align__(16) __nv_bfloat16 Vs[64 * SSTR];

    const int tid  = threadIdx.x;
    const int warp = tid >> 5;
    const int lane = tid & 31;
    const int bh   = blockIdx.y;
    const int q0   = blockIdx.x * 64;

    const __nv_bfloat16* qg = g_qh + ((size_t)bh * Sc + q0) * HDc;
    const __nv_bfloat16* kg = g_kh + (size_t)bh * Sc * HDc;
    const __nv_bfloat16* vg = g_vh + (size_t)bh * Sc * HDc;

    // ---- load Q tile (64 x 64 bf16) ----
#pragma unroll
    for (int u = 0; u < 4; u++) {
        int i = u * 128 + tid;           // 0..511 uint4 chunks
        int r = i >> 3, c = i & 7;       // row, 16B chunk
        *(uint4*)&Qs[r * SSTR + c * 8] = *(const uint4*)(qg + (size_t)r * HDc + c * 8);
    }
    __syncthreads();

    const uint32_t qs_b = (uint32_t)__cvta_generic_to_shared(Qs);
    const uint32_t ks_b = (uint32_t)__cvta_generic_to_shared(Ks);
    const uint32_t vs_b = (uint32_t)__cvta_generic_to_shared(Vs);

    // ---- Q fragments (held in regs for whole kernel) ----
    uint32_t qf[4][4];
    {
        int row = (lane & 15);
        int colo = (lane >= 16) ? 8 : 0;
#pragma unroll
        for (int ks = 0; ks < 4; ks++) {
            uint32_t a = qs_b + ((warp * 16 + row) * SSTR + ks * 16 + colo) * 2;
            LDSM4(qf[ks][0], qf[ks][1], qf[ks][2], qf[ks][3], a);
        }
    }

    // per-lane ldmatrix address components
    const int q8 = lane >> 3;                    // 0..3 address group
    const int kRow = ((q8 >> 1) * 8) + (lane & 7);
    const int kCol = (q8 & 1) * 8;
    const int vRow = ((q8 & 1) * 8) + (lane & 7);
    const int vCol = (q8 >> 1) * 8;

    float o[8][4];
#pragma unroll
    for (int nt = 0; nt < 8; nt++)
#pragma unroll
        for (int i = 0; i < 4; i++) o[nt][i] = 0.f;
    float m0 = -INFINITY, m1 = -INFINITY, l0 = 0.f, l1 = 0.f;

    for (int j0 = 0; j0 < Sc; j0 += 64) {
        __syncthreads();
        // ---- load K,V tiles (64 x 64 bf16 each) ----
#pragma unroll
        for (int u = 0; u < 4; u++) {
            int i = u * 128 + tid;
            int r = i >> 3, c = i & 7;
            *(uint4*)&Ks[r * SSTR + c * 8] = *(const uint4*)(kg + (size_t)(j0 + r) * HDc + c * 8);
            *(uint4*)&Vs[r * SSTR + c * 8] = *(const uint4*)(vg + (size_t)(j0 + r) * HDc + c * 8);
        }
        __syncthreads();

        // ---- S = Q K^T  (16 x 64 per warp) ----
        float s[8][4];
#pragma unroll
        for (int nt = 0; nt < 8; nt++)
#pragma unroll
            for (int i = 0; i < 4; i++) s[nt][i] = 0.f;

#pragma unroll
        for (int ks = 0; ks < 4; ks++) {
            uint32_t kf[16];
#pragma unroll
            for (int ntp = 0; ntp < 4; ntp++) {
                uint32_t a = ks_b + ((ntp * 16 + kRow) * SSTR + ks * 16 + kCol) * 2;
                LDSM4(kf[4*ntp], kf[4*ntp+1], kf[4*ntp+2], kf[4*ntp+3], a);
            }
#pragma unroll
            for (int ntp = 0; ntp < 4; ntp++) {
                MMA16816(s[2*ntp],   qf[ks], kf[4*ntp],   kf[4*ntp+1]);
                MMA16816(s[2*ntp+1], qf[ks], kf[4*ntp+2], kf[4*ntp+3]);
            }
        }

        // ---- online softmax (rows g and g+8) ----
        float mt0 = -INFINITY, mt1 = -INFINITY;
#pragma unroll
        for (int nt = 0; nt < 8; nt++) {
            mt0 = fmaxf(mt0, fmaxf(s[nt][0], s[nt][1]));
            mt1 = fmaxf(mt1, fmaxf(s[nt][2], s[nt][3]));
        }
        mt0 = fmaxf(mt0, __shfl_xor_sync(0xffffffffu, mt0, 1));
        mt0 = fmaxf(mt0, __shfl_xor_sync(0xffffffffu, mt0, 2));
        mt1 = fmaxf(mt1, __shfl_xor_sync(0xffffffffu, mt1, 1));
        mt1 = fmaxf(mt1, __shfl_xor_sync(0xffffffffu, mt1, 2));

        float nm0 = fmaxf(m0, mt0), nm1 = fmaxf(m1, mt1);
        float c0 = __expf(m0 - nm0), c1 = __expf(m1 - nm1);
        float ps0 = 0.f, ps1 = 0.f;
#pragma unroll
        for (int nt = 0; nt < 8; nt++) {
            s[nt][0] = __expf(s[nt][0] - nm0);
            s[nt][1] = __expf(s[nt][1] - nm0);
            s[nt][2] = __expf(s[nt][2] - nm1);
            s[nt][3] = __expf(s[nt][3] - nm1);
            ps0 += s[nt][0] + s[nt][1];
            ps1 += s[nt][2] + s[nt][3];
        }
        ps0 += __shfl_xor_sync(0xffffffffu, ps0, 1);
        ps0 += __shfl_xor_sync(0xffffffffu, ps0, 2);
        ps1 += __shfl_xor_sync(0xffffffffu, ps1, 1);
        ps1 += __shfl_xor_sync(0xffffffffu, ps1, 2);
        l0 = l0 * c0 + ps0;
        l1 = l1 * c1 + ps1;
        m0 = nm0; m1 = nm1;

#pragma unroll
        for (int nt = 0; nt < 8; nt++) {
            o[nt][0] *= c0; o[nt][1] *= c0;
            o[nt][2] *= c1; o[nt][3] *= c1;
        }

        // ---- pack P to bf16 A-fragments ----
        uint32_t pf[4][4];
#pragma unroll
        for (int ks2 = 0; ks2 < 4; ks2++) {
            pf[ks2][0] = pack_bf16(s[2*ks2][0],   s[2*ks2][1]);
            pf[ks2][1] = pack_bf16(s[2*ks2][2],   s[2*ks2][3]);
            pf[ks2][2] = pack_bf16(s[2*ks2+1][0], s[2*ks2+1][1]);
            pf[ks2][3] = pack_bf16(s[2*ks2+1][2], s[2*ks2+1][3]);
        }

        // ---- O += P V ----
#pragma unroll
        for (int ks2 = 0; ks2 < 4; ks2++) {
            uint32_t vf[16];
#pragma unroll
            for (int ntp = 0; ntp < 4; ntp++) {
                uint32_t a = vs_b + ((ks2 * 16 + vRow) * SSTR + ntp * 16 + vCol) * 2;
                LDSM4T(vf[4*ntp], vf[4*ntp+1], vf[4*ntp+2], vf[4*ntp+3], a);
            }
#pragma unroll
            for (int ntp = 0; ntp < 4; ntp++) {
                MMA16816(o[2*ntp],   pf[ks2], vf[4*ntp],   vf[4*ntp+1]);
                MMA16816(o[2*ntp+1], pf[ks2], vf[4*ntp+2], vf[4*ntp+3]);
            }
        }
    }

    // ---- epilogue: normalize and write [b, s, h*64+d] ----
    float inv0 = 1.f / l0, inv1 = 1.f / l1;
    int b_ = bh / Hc, h_ = bh % Hc;
    int qrow = q0 + warp * 16 + (lane >> 2);
    float* outp = g_attn + ((size_t)(b_ * Sc + qrow)) * DMc + h_ * HDc;
#pragma unroll
    for (int nt = 0; nt < 8; nt++) {
        int col = nt * 8 + 2 * (lane & 3);
        float2 r0 = make_float2(o[nt][0] * inv0, o[nt][1] * inv0);
        float2 r1 = make_float2(o[nt][2] * inv1, o[nt][3] * inv1);
        *(float2*)(outp + col)            = r0;
        *(float2*)(outp + 8 * DMc + col)  = r1;
    }
}

// ---------------------------------------------------------------------------
// LayerNorm over last dim (768), one block per row.
// ---------------------------------------------------------------------------
__global__ __launch_bounds__(256) void ln_kernel(const float* __restrict__ g,
                                                 const float* __restrict__ bb,
                                                 float* __restrict__ out) {
    int row = blockIdx.x;
    const float* yp = g_y + (size_t)row * DMc;
    int tid = threadIdx.x;
    float v0 = yp[tid], v1 = yp[tid + 256], v2 = yp[tid + 512];
    float s = v0 + v1 + v2;

    __shared__ float red[8];
    __shared__ float bc;
#pragma unroll
    for (int o_ = 16; o_ > 0; o_ >>= 1) s += __shfl_xor_sync(0xffffffffu, s, o_);
    if ((tid & 31) == 0) red[tid >> 5] = s;
    __syncthreads();
    if (tid == 0) {
        float tsum = 0.f;
#pragma unroll
        for (int i = 0; i < 8; i++) tsum += red[i];
        bc = tsum;
    }
    __syncthreads();
    float mu = bc * (1.0f / (float)DMc);
    float d0 = v0 - mu, d1 = v1 - mu, d2 = v2 - mu;
    float sq = d0 * d0 + d1 * d1 + d2 * d2;
    __syncthreads();
#pragma unroll
    for (int o_ = 16; o_ > 0; o_ >>= 1) sq += __shfl_xor_sync(0xffffffffu, sq, o_);
    if ((tid & 31) == 0) red[tid >> 5] = sq;
    __syncthreads();
    if (tid == 0) {
        float tsum = 0.f;
#pragma unroll
        for (int i = 0; i < 8; i++) tsum += red[i];
        bc = tsum;
    }
    __syncthreads();
    float var = bc * (1.0f / (float)DMc);
    float inv = rsqrtf(var + 1e-12f);
    size_t base = (size_t)row * DMc;
    out[base + tid]       = d0 * inv * g[tid]       + bb[tid];
    out[base + tid + 256] = d1 * inv * g[tid + 256] + bb[tid + 256];
    out[base + tid + 512] = d2 * inv * g[tid + 512] + bb[tid + 512];
}

// ---------------------------------------------------------------------------
extern "C" void kernel_launch(void* const* d_in, const int* in_sizes, int n_in,
                              void* d_out, int out_size) {
    const float* hidden = (const float*)d_in[0];
    const float* cosp   = (const float*)d_in[1];
    const float* sinp   = (const float*)d_in[2];
    const float* Wq     = (const float*)d_in[3];
    const float* bq     = (const float*)d_in[4];
    const float* Wk     = (const float*)d_in[5];
    const float* bk     = (const float*)d_in[6];
    const float* Wv     = (const float*)d_in[7];
    const float* bv     = (const float*)d_in[8];
    const float* Wo     = (const float*)d_in[9];
    const float* ln_g   = (const float*)d_in[10];
    const float* ln_b   = (const float*)d_in[11];
    float* out = (float*)d_out;

    dim3 ggrid(DMc / 64, (Bc * Sc) / 64);   // (12, 128)
    gemm_nt<0><<<ggrid, 256>>>(hidden, Wq, bq, nullptr, 0);
    gemm_nt<0><<<ggrid, 256>>>(hidden, Wk, bk, nullptr, 1);
    gemm_nt<0><<<ggrid, 256>>>(hidden, Wv, bv, nullptr, 2);

    dim3 rgrid((BHc * Sc + 255) / 256, 2);
    rope_kernel<<<rgrid, 256>>>(cosp, sinp);

    dim3 agrid(Sc / 64, BHc);               // (64, 24)
    flash_mma_kernel<<<agrid, 128>>>();

    gemm_nt<1><<<ggrid, 256>>>(nullptr, Wo, nullptr, hidden, 0);

    ln_kernel<<<Bc * Sc, 256>>>(ln_g, ln_b, out);
}

// round 3
// speedup vs baseline: 8.2150x; 2.6795x over previous
#include <cuda_runtime.h>
#include <cuda_bf16.h>
#include <math.h>
#include <stdint.h>

#define Bc 2
#define Sc 4096
#define DMc 768
#define Hc 12
#define HDc 64
#define BHc (Bc*Hc)

// Scratch (allocation-free rule: __device__ globals)
__device__ __nv_bfloat16 g_xh[(size_t)Bc*Sc*DMc];     // bf16 hidden
__device__ __nv_bfloat16 g_wh[4][(size_t)DMc*DMc];    // bf16 Wq,Wk,Wv,Wo
__device__ __nv_bfloat16 g_qh[(size_t)BHc*Sc*HDc];    // bf16 q (RoPE'd, * 1/64)
__device__ __nv_bfloat16 g_kh[(size_t)BHc*Sc*HDc];    // bf16 k (RoPE'd)
__device__ __nv_bfloat16 g_vh[(size_t)BHc*Sc*HDc];    // bf16 v
__device__ __nv_bfloat16 g_attnh[(size_t)Bc*Sc*DMc];  // bf16 attn out
__device__ float g_y[(size_t)Bc*Sc*DMc];              // fp32 pre-LN

// ---------------------------------------------------------------------------
// fp32 -> bf16 convert (vectorized, grid-stride)
// ---------------------------------------------------------------------------
__global__ __launch_bounds__(256) void f2b_kernel(const float* __restrict__ src,
                                                  __nv_bfloat16* __restrict__ dst,
                                                  int n4) {
    int i = blockIdx.x * blockDim.x + threadIdx.x;
    if (i >= n4) return;
    float4 v = *(const float4*)(src + (size_t)i * 4);
    __nv_bfloat162 a = __floats2bfloat162_rn(v.x, v.y);
    __nv_bfloat162 b = __floats2bfloat162_rn(v.z, v.w);
    *(__nv_bfloat162*)(dst + (size_t)i * 4 + 0) = a;
    *(__nv_bfloat162*)(dst + (size_t)i * 4 + 2) = b;
}

// ---------------------------------------------------------------------------
// MMA helpers (shared by gemm + flash)
// ---------------------------------------------------------------------------
__device__ __forceinline__ uint32_t pack_bf16(float lo, float hi) {
    __nv_bfloat162 h = __floats2bfloat162_rn(lo, hi);
    return *reinterpret_cast<uint32_t*>(&h);
}

#define LDSM4(r0,r1,r2,r3,addr) \
    asm volatile("ldmatrix.sync.aligned.m8n8.x4.shared.b16 {%0,%1,%2,%3},[%4];" \
                 : "=r"(r0),"=r"(r1),"=r"(r2),"=r"(r3) : "r"(addr))
#define LDSM4T(r0,r1,r2,r3,addr) \
    asm volatile("ldmatrix.sync.aligned.m8n8.x4.trans.shared.b16 {%0,%1,%2,%3},[%4];" \
                 : "=r"(r0),"=r"(r1),"=r"(r2),"=r"(r3) : "r"(addr))
#define MMA16816(c, a, b0, b1) \
    asm volatile("mma.sync.aligned.m16n8k16.row.col.f32.bf16.bf16.f32 " \
                 "{%0,%1,%2,%3},{%4,%5,%6,%7},{%8,%9},{%0,%1,%2,%3};" \
                 : "+f"((c)[0]),"+f"((c)[1]),"+f"((c)[2]),"+f"((c)[3]) \
                 : "r"((a)[0]),"r"((a)[1]),"r"((a)[2]),"r"((a)[3]),"r"(b0),"r"(b1))

// ---------------------------------------------------------------------------
// Tensor-core GEMM:  C[M,N] = X[M,K] @ W[N,K]^T ; M=8192, N=K=768, bf16 in.
// CTA: 128 threads / 4 warps, tile 128M x 64N, K-chunks of 64.
// MODE 0: sel 0 -> RoPE+1/64 -> g_qh ; sel 1 -> RoPE -> g_kh ;
//         sel 2 -> +bias -> g_vh.   All in [b,h,s,d] bf16.
// MODE 1: g_y[row,col] = acc + resid[row,col]  (X = g_attnh)
// ---------------------------------------------------------------------------
#define GSTR 72
template <int MODE>
__global__ __launch_bounds__(128) void gemm_tc(const __nv_bfloat16* __restrict__ X,
                                               const __nv_bfloat16* __restrict__ W,
                                               const float* __restrict__ bias,
                                               const float* __restrict__ resid,
                                               const float* __restrict__ cosp,
                                               const float* __restrict__ sinp,
                                               int sel) {
    __shared__ __align__(16) __nv_bfloat16 Xs[128 * GSTR];
    __shared__ __align__(16) __nv_bfloat16 Ws[64 * GSTR];

    const int tid  = threadIdx.x;
    const int warp = tid >> 5;
    const int lane = tid & 31;
    const int rowBase = blockIdx.y * 128;
    const int colBase = blockIdx.x * 64;

    const uint32_t xs_b = (uint32_t)__cvta_generic_to_shared(Xs);
    const uint32_t ws_b = (uint32_t)__cvta_generic_to_shared(Ws);

    float acc[2][8][4];
#pragma unroll
    for (int mt = 0; mt < 2; mt++)
#pragma unroll
        for (int nt = 0; nt < 8; nt++)
#pragma unroll
            for (int i = 0; i < 4; i++) acc[mt][nt][i] = 0.f;

    const int q8 = lane >> 3;
    const int bRow = ((q8 >> 1) * 8) + (lane & 7);
    const int bCol = (q8 & 1) * 8;
    const int aRow = lane & 15;
    const int aCol = (lane >> 4) * 8;

    for (int kb = 0; kb < DMc; kb += 64) {
        __syncthreads();
#pragma unroll
        for (int u = 0; u < 8; u++) {
            int i = u * 128 + tid;
            int r = i >> 3, c = i & 7;
            *(uint4*)&Xs[r * GSTR + c * 8] =
                *(const uint4*)(X + (size_t)(rowBase + r) * DMc + kb + c * 8);
        }
#pragma unroll
        for (int u = 0; u < 4; u++) {
            int i = u * 128 + tid;
            int r = i >> 3, c = i & 7;
            *(uint4*)&Ws[r * GSTR + c * 8] =
                *(const uint4*)(W + (size_t)(colBase + r) * DMc + kb + c * 8);
        }
        __syncthreads();

#pragma unroll
        for (int ks = 0; ks < 4; ks++) {
            uint32_t af[2][4];
#pragma unroll
            for (int mt = 0; mt < 2; mt++) {
                uint32_t a = xs_b + ((warp * 32 + mt * 16 + aRow) * GSTR + ks * 16 + aCol) * 2;
                LDSM4(af[mt][0], af[mt][1], af[mt][2], af[mt][3], a);
            }
            uint32_t bf[16];
#pragma unroll
            for (int ntp = 0; ntp < 4; ntp++) {
                uint32_t a = ws_b + ((ntp * 16 + bRow) * GSTR + ks * 16 + bCol) * 2;
                LDSM4(bf[4*ntp], bf[4*ntp+1], bf[4*ntp+2], bf[4*ntp+3], a);
            }
#pragma unroll
            for (int mt = 0; mt < 2; mt++)
#pragma unroll
                for (int ntp = 0; ntp < 4; ntp++) {
                    MMA16816(acc[mt][2*ntp],   af[mt], bf[4*ntp],   bf[4*ntp+1]);
                    MMA16816(acc[mt][2*ntp+1], af[mt], bf[4*ntp+2], bf[4*ntp+3]);
                }
        }
    }

    // ---- epilogue ----
    if (MODE == 1) {
#pragma unroll
        for (int mt = 0; mt < 2; mt++) {
            int r0 = rowBase + warp * 32 + mt * 16 + (lane >> 2);
#pragma unroll
            for (int nt = 0; nt < 8; nt++) {
                int col = colBase + nt * 8 + 2 * (lane & 3);
                size_t o0 = (size_t)r0 * DMc + col;
                size_t o1 = (size_t)(r0 + 8) * DMc + col;
                float2 w0 = make_float2(acc[mt][nt][0] + resid[o0],
                                        acc[mt][nt][1] + resid[o0 + 1]);
                float2 w1 = make_float2(acc[mt][nt][2] + resid[o1],
                                        acc[mt][nt][3] + resid[o1 + 1]);
                *(float2*)(g_y + o0) = w0;
                *(float2*)(g_y + o1) = w1;
            }
        }
        return;
    }

    // MODE 0
    __nv_bfloat16* dst = (sel == 0) ? g_qh : (sel == 1) ? g_kh : g_vh;
    const int h_ = colBase >> 6;
    const float scale = (sel == 0) ? (1.0f / (float)HDc) : 1.0f;

#pragma unroll
    for (int mt = 0; mt < 2; mt++) {
        int r0 = rowBase + warp * 32 + mt * 16 + (lane >> 2);
        int r1 = r0 + 8;
        int b0_ = r0 >> 12, s0_ = r0 & (Sc - 1);
        int b1_ = r1 >> 12, s1_ = r1 & (Sc - 1);
        size_t base0 = (((size_t)(b0_ * Hc + h_)) * Sc + s0_) * HDc;
        size_t base1 = (((size_t)(b1_ * Hc + h_)) * Sc + s1_) * HDc;

        if (sel == 2) {
#pragma unroll
            for (int nt = 0; nt < 8; nt++) {
                int d = nt * 8 + 2 * (lane & 3);
                float b_lo = bias[d], b_hi = bias[d + 1];
                *(__nv_bfloat162*)(dst + base0 + d) =
                    __floats2bfloat162_rn(acc[mt][nt][0] + b_lo, acc[mt][nt][1] + b_hi);
                *(__nv_bfloat162*)(dst + base1 + d) =
                    __floats2bfloat162_rn(acc[mt][nt][2] + b_lo, acc[mt][nt][3] + b_hi);
            }
        } else {
            // RoPE: pair (d, d+32) lives in (nt, nt+4)
#pragma unroll
            for (int nt = 0; nt < 4; nt++) {
                int d = nt * 8 + 2 * (lane & 3);
                float bl = bias[d],      bh = bias[d + 1];
                float bL = bias[d + 32], bH = bias[d + 33];
                float2 c0 = *(const float2*)(cosp + (size_t)s0_ * HDc + d);
                float2 sn0 = *(const float2*)(sinp + (size_t)s0_ * HDc + d);
                float2 c1 = *(const float2*)(cosp + (size_t)s1_ * HDc + d);
                float2 sn1 = *(const float2*)(sinp + (size_t)s1_ * HDc + d);

                // row r0
                {
                    float xa0 = acc[mt][nt][0] + bl,  xa1 = acc[mt][nt][1] + bh;
                    float xb0 = acc[mt][nt+4][0] + bL, xb1 = acc[mt][nt+4][1] + bH;
                    float lo0 = (xa0 * c0.x - xb0 * sn0.x) * scale;
                    float lo1 = (xa1 * c0.y - xb1 * sn0.y) * scale;
                    float hi0 = (xb0 * c0.x + xa0 * sn0.x) * scale;
                    float hi1 = (xb1 * c0.y + xa1 * sn0.y) * scale;
                    *(__nv_bfloat162*)(dst + base0 + d)      = __floats2bfloat162_rn(lo0, lo1);
                    *(__nv_bfloat162*)(dst + base0 + d + 32) = __floats2bfloat162_rn(hi0, hi1);
                }
                // row r1
                {
                    float xa0 = acc[mt][nt][2] + bl,  xa1 = acc[mt][nt][3] + bh;
                    float xb0 = acc[mt][nt+4][2] + bL, xb1 = acc[mt][nt+4][3] + bH;
                    float lo0 = (xa0 * c1.x - xb0 * sn1.x) * scale;
                    float lo1 = (xa1 * c1.y - xb1 * sn1.y) * scale;
                    float hi0 = (xb0 * c1.x + xa0 * sn1.x) * scale;
                    float hi1 = (xb1 * c1.y + xa1 * sn1.y) * scale;
                    *(__nv_bfloat162*)(dst + base1 + d)      = __floats2bfloat162_rn(lo0, lo1);
                    *(__nv_bfloat162*)(dst + base1 + d + 32) = __floats2bfloat162_rn(hi0, hi1);
                }
            }
        }
    }
}

// ---------------------------------------------------------------------------
// Flash attention with bf16 mma.sync, fp32 softmax. Writes bf16 g_attnh.
// ---------------------------------------------------------------------------
#define SSTR 72

__global__ __launch_bounds__(128) void flash_mma_kernel() {
    __shared__ __align__(16) __nv_bfloat16 Qs[64 * SSTR];
    __shared__ __align__(16) __nv_bfloat16 Ks[64 * SSTR];
    __shared__ __align__(16) __nv_bfloat16 Vs[64 * SSTR];

    const int tid  = threadIdx.x;
    const int warp = tid >> 5;
    const int lane = tid & 31;
    const int bh   = blockIdx.y;
    const int q0   = blockIdx.x * 64;

    const __nv_bfloat16* qg = g_qh + ((size_t)bh * Sc + q0) * HDc;
    const __nv_bfloat16* kg = g_kh + (size_t)bh * Sc * HDc;
    const __nv_bfloat16* vg = g_vh + (size_t)bh * Sc * HDc;

#pragma unroll
    for (int u = 0; u < 4; u++) {
        int i = u * 128 + tid;
        int r = i >> 3, c = i & 7;
        *(uint4*)&Qs[r * SSTR + c * 8] = *(const uint4*)(qg + (size_t)r * HDc + c * 8);
    }
    __syncthreads();

    const uint32_t qs_b = (uint32_t)__cvta_generic_to_shared(Qs);
    const uint32_t ks_b = (uint32_t)__cvta_generic_to_shared(Ks);
    const uint32_t vs_b = (uint32_t)__cvta_generic_to_shared(Vs);

    uint32_t qf[4][4];
    {
        int row = (lane & 15);
        int colo = (lane >= 16) ? 8 : 0;
#pragma unroll
        for (int ks = 0; ks < 4; ks++) {
            uint32_t a = qs_b + ((warp * 16 + row) * SSTR + ks * 16 + colo) * 2;
            LDSM4(qf[ks][0], qf[ks][1], qf[ks][2], qf[ks][3], a);
        }
    }

    const int q8 = lane >> 3;
    const int kRow = ((q8 >> 1) * 8) + (lane & 7);
    const int kCol = (q8 & 1) * 8;
    const int vRow = ((q8 & 1) * 8) + (lane & 7);
    const int vCol = (q8 >> 1) * 8;

    float o[8][4];
#pragma unroll
    for (int nt = 0; nt < 8; nt++)
#pragma unroll
        for (int i = 0; i < 4; i++) o[nt][i] = 0.f;
    float m0 = -INFINITY, m1 = -INFINITY, l0 = 0.f, l1 = 0.f;

    for (int j0 = 0; j0 < Sc; j0 += 64) {
        __syncthreads();
#pragma unroll
        for (int u = 0; u < 4; u++) {
            int i = u * 128 + tid;
            int r = i >> 3, c = i & 7;
            *(uint4*)&Ks[r * SSTR + c * 8] = *(const uint4*)(kg + (size_t)(j0 + r) * HDc + c * 8);
            *(uint4*)&Vs[r * SSTR + c * 8] = *(const uint4*)(vg + (size_t)(j0 + r) * HDc + c * 8);
        }
        __syncthreads();

        float s[8][4];
#pragma unroll
        for (int nt = 0; nt < 8; nt++)
#pragma unroll
            for (int i = 0; i < 4; i++) s[nt][i] = 0.f;

#pragma unroll
        for (int ks = 0; ks < 4; ks++) {
            uint32_t kf[16];
#pragma unroll
            for (int ntp = 0; ntp < 4; ntp++) {
                uint32_t a = ks_b + ((ntp * 16 + kRow) * SSTR + ks * 16 + kCol) * 2;
                LDSM4(kf[4*ntp], kf[4*ntp+1], kf[4*ntp+2], kf[4*ntp+3], a);
            }
#pragma unroll
            for (int ntp = 0; ntp < 4; ntp++) {
                MMA16816(s[2*ntp],   qf[ks], kf[4*ntp],   kf[4*ntp+1]);
                MMA16816(s[2*ntp+1], qf[ks], kf[4*ntp+2], kf[4*ntp+3]);
            }
        }

        float mt0 = -INFINITY, mt1 = -INFINITY;
#pragma unroll
        for (int nt = 0; nt < 8; nt++) {
            mt0 = fmaxf(mt0, fmaxf(s[nt][0], s[nt][1]));
            mt1 = fmaxf(mt1, fmaxf(s[nt][2], s[nt][3]));
        }
        mt0 = fmaxf(mt0, __shfl_xor_sync(0xffffffffu, mt0, 1));
        mt0 = fmaxf(mt0, __shfl_xor_sync(0xffffffffu, mt0, 2));
        mt1 = fmaxf(mt1, __shfl_xor_sync(0xffffffffu, mt1, 1));
        mt1 = fmaxf(mt1, __shfl_xor_sync(0xffffffffu, mt1, 2));

        float nm0 = fmaxf(m0, mt0), nm1 = fmaxf(m1, mt1);
        float c0 = __expf(m0 - nm0), c1 = __expf(m1 - nm1);
        float ps0 = 0.f, ps1 = 0.f;
#pragma unroll
        for (int nt = 0; nt < 8; nt++) {
            s[nt][0] = __expf(s[nt][0] - nm0);
            s[nt][1] = __expf(s[nt][1] - nm0);
            s[nt][2] = __expf(s[nt][2] - nm1);
            s[nt][3] = __expf(s[nt][3] - nm1);
            ps0 += s[nt][0] + s[nt][1];
            ps1 += s[nt][2] + s[nt][3];
        }
        ps0 += __shfl_xor_sync(0xffffffffu, ps0, 1);
        ps0 += __shfl_xor_sync(0xffffffffu, ps0, 2);
        ps1 += __shfl_xor_sync(0xffffffffu, ps1, 1);
        ps1 += __shfl_xor_sync(0xffffffffu, ps1, 2);
        l0 = l0 * c0 + ps0;
        l1 = l1 * c1 + ps1;
        m0 = nm0; m1 = nm1;

#pragma unroll
        for (int nt = 0; nt < 8; nt++) {
            o[nt][0] *= c0; o[nt][1] *= c0;
            o[nt][2] *= c1; o[nt][3] *= c1;
        }

        uint32_t pf[4][4];
#pragma unroll
        for (int ks2 = 0; ks2 < 4; ks2++) {
            pf[ks2][0] = pack_bf16(s[2*ks2][0],   s[2*ks2][1]);
            pf[ks2][1] = pack_bf16(s[2*ks2][2],   s[2*ks2][3]);
            pf[ks2][2] = pack_bf16(s[2*ks2+1][0], s[2*ks2+1][1]);
            pf[ks2][3] = pack_bf16(s[2*ks2+1][2], s[2*ks2+1][3]);
        }

#pragma unroll
        for (int ks2 = 0; ks2 < 4; ks2++) {
            uint32_t vf[16];
#pragma unroll
            for (int ntp = 0; ntp < 4; ntp++) {
                uint32_t a = vs_b + ((ks2 * 16 + vRow) * SSTR + ntp * 16 + vCol) * 2;
                LDSM4T(vf[4*ntp], vf[4*ntp+1], vf[4*ntp+2], vf[4*ntp+3], a);
            }
#pragma unroll
            for (int ntp = 0; ntp < 4; ntp++) {
                MMA16816(o[2*ntp],   pf[ks2], vf[4*ntp],   vf[4*ntp+1]);
                MMA16816(o[2*ntp+1], pf[ks2], vf[4*ntp+2], vf[4*ntp+3]);
            }
        }
    }

    float inv0 = 1.f / l0, inv1 = 1.f / l1;
    int b_ = bh / Hc, h_ = bh % Hc;
    int qrow = q0 + warp * 16 + (lane >> 2);
    __nv_bfloat16* outp = g_attnh + ((size_t)(b_ * Sc + qrow)) * DMc + h_ * HDc;
#pragma unroll
    for (int nt = 0; nt < 8; nt++) {
        int col = nt * 8 + 2 * (lane & 3);
        *(__nv_bfloat162*)(outp + col) =
            __floats2bfloat162_rn(o[nt][0] * inv0, o[nt][1] * inv0);
        *(__nv_bfloat162*)(outp + 8 * DMc + col) =
            __floats2bfloat162_rn(o[nt][2] * inv1, o[nt][3] * inv1);
    }
}

// ---------------------------------------------------------------------------
// LayerNorm over last dim (768), one block per row.
// ---------------------------------------------------------------------------
__global__ __launch_bounds__(256) void ln_kernel(const float* __restrict__ g,
                                                 const float* __restrict__ bb,
                                                 float* __restrict__ out) {
    int row = blockIdx.x;
    const float* yp = g_y + (size_t)row * DMc;
    int tid = threadIdx.x;
    float v0 = yp[tid], v1 = yp[tid + 256], v2 = yp[tid + 512];
    float s = v0 + v1 + v2;

    __shared__ float red[8];
    __shared__ float bc;
#pragma unroll
    for (int o_ = 16; o_ > 0; o_ >>= 1) s += __shfl_xor_sync(0xffffffffu, s, o_);
    if ((tid & 31) == 0) red[tid >> 5] = s;
    __syncthreads();
    if (tid == 0) {
        float tsum = 0.f;
#pragma unroll
        for (int i = 0; i < 8; i++) tsum += red[i];
        bc = tsum;
    }
    __syncthreads();
    float mu = bc * (1.0f / (float)DMc);
    float d0 = v0 - mu, d1 = v1 - mu, d2 = v2 - mu;
    float sq = d0 * d0 + d1 * d1 + d2 * d2;
    __syncthreads();
#pragma unroll
    for (int o_ = 16; o_ > 0; o_ >>= 1) sq += __shfl_xor_sync(0xffffffffu, sq, o_);
    if ((tid & 31) == 0) red[tid >> 5] = sq;
    __syncthreads();
    if (tid == 0) {
        float tsum = 0.f;
#pragma unroll
        for (int i = 0; i < 8; i++) tsum += red[i];
        bc = tsum;
    }
    __syncthreads();
    float var = bc * (1.0f / (float)DMc);
    float inv = rsqrtf(var + 1e-12f);
    size_t base = (size_t)row * DMc;
    out[base + tid]       = d0 * inv * g[tid]       + bb[tid];
    out[base + tid + 256] = d1 * inv * g[tid + 256] + bb[tid + 256];
    out[base + tid + 512] = d2 * inv * g[tid + 512] + bb[tid + 512];
}

// ---------------------------------------------------------------------------
extern "C" void kernel_launch(void* const* d_in, const int* in_sizes, int n_in,
                              void* d_out, int out_size) {
    const float* hidden = (const float*)d_in[0];
    const float* cosp   = (const float*)d_in[1];
    const float* sinp   = (const float*)d_in[2];
    const float* Wq     = (const float*)d_in[3];
    const float* bq     = (const float*)d_in[4];
    const float* Wk     = (const float*)d_in[5];
    const float* bk     = (const float*)d_in[6];
    const float* Wv     = (const float*)d_in[7];
    const float* bv     = (const float*)d_in[8];
    const float* Wo     = (const float*)d_in[9];
    const float* ln_g   = (const float*)d_in[10];
    const float* ln_b   = (const float*)d_in[11];
    float* out = (float*)d_out;

    __nv_bfloat16* xh; cudaGetSymbolAddress((void**)&xh, g_xh);
    __nv_bfloat16* wh; cudaGetSymbolAddress((void**)&wh, g_wh);
    __nv_bfloat16* ah; cudaGetSymbolAddress((void**)&ah, g_attnh);

    // converts
    int nH4 = (Bc * Sc * DMc) / 4;
    int nW4 = (DMc * DMc) / 4;
    f2b_kernel<<<(nH4 + 255) / 256, 256>>>(hidden, xh, nH4);
    f2b_kernel<<<(nW4 + 255) / 256, 256>>>(Wq, wh + 0 * (size_t)DMc * DMc, nW4);
    f2b_kernel<<<(nW4 + 255) / 256, 256>>>(Wk, wh + 1 * (size_t)DMc * DMc, nW4);
    f2b_kernel<<<(nW4 + 255) / 256, 256>>>(Wv, wh + 2 * (size_t)DMc * DMc, nW4);
    f2b_kernel<<<(nW4 + 255) / 256, 256>>>(Wo, wh + 3 * (size_t)DMc * DMc, nW4);

    dim3 ggrid(DMc / 64, (Bc * Sc) / 128);   // (12, 64)
    gemm_tc<0><<<ggrid, 128>>>(xh, wh + 0 * (size_t)DMc * DMc, bq, nullptr, cosp, sinp, 0);
    gemm_tc<0><<<ggrid, 128>>>(xh, wh + 1 * (size_t)DMc * DMc, bk, nullptr, cosp, sinp, 1);
    gemm_tc<0><<<ggrid, 128>>>(xh, wh + 2 * (size_t)DMc * DMc, bv, nullptr, cosp, sinp, 2);

    dim3 agrid(Sc / 64, BHc);                // (64, 24)
    flash_mma_kernel<<<agrid, 128>>>();

    gemm_tc<1><<<ggrid, 128>>>(ah, wh + 3 * (size_t)DMc * DMc, nullptr, hidden, cosp, sinp, 3);

    ln_kernel<<<Bc * Sc, 256>>>(ln_g, ln_b, out);
}